// round 5
// baseline (speedup 1.0000x reference)
#include <cuda_runtime.h>
#include <math.h>

// Problem constants (FrameReducer: N=16, T=2048, C=512, V=500)
#define PN 16
#define PT 2048
#define PC 512
#define PV 500
#define NWORDS (PT / 32)   // 64 mask words per row
#define TPB 256

// Scratch (device globals; no allocation allowed)
__device__ unsigned g_mask[PN * NWORDS]; // keep-bitmask per row
__device__ int g_src[PN * PT];           // g_src[n*PT + r] = source t for rank r
__device__ int g_lens[PN];               // lens_fr per batch row
__device__ unsigned g_bar_cnt = 0;       // grid barrier arrival counter
__device__ unsigned g_bar_gen = 0;       // grid barrier generation

// threshold: float32(log(0.9)) — matches jnp float32 weak-typed comparison
#define LOG09 (-0.10536051565782628f)

// ---------------------------------------------------------------------------
// Software grid barrier. Requires all nblocks co-resident (grid <= #SMs,
// 256 threads, low regs -> guaranteed). Generation-based: no reset hazard
// across graph replays (state returns to {cnt=0, gen+=2} each launch).
// Waiters spin on the generation word with nanosleep backoff.
// ---------------------------------------------------------------------------
__device__ __forceinline__ void grid_barrier(int nblocks) {
    __syncthreads();
    if (threadIdx.x == 0) {
        volatile unsigned* vgen = &g_bar_gen;
        const unsigned gen = *vgen;          // read BEFORE arriving (barrier
        __threadfence();                     // can't complete without us)
        if (atomicAdd(&g_bar_cnt, 1u) == (unsigned)(nblocks - 1)) {
            g_bar_cnt = 0;                   // reset BEFORE release
            __threadfence();
            atomicAdd(&g_bar_gen, 1u);       // release
        } else {
            while (*vgen == gen) { __nanosleep(64); }
        }
        __threadfence();
    }
    __syncthreads();
}

// ---------------------------------------------------------------------------
// Robust x_lens read: JAX with x64 disabled dumps int32 despite astype(int64).
// Detect dtype from the first 64 bytes only (always in-bounds):
//   int64 layout: words[1,3,...,15] are high words of values in [1,2048] -> 0
//   int32 layout: words[1,3,...,15] are lens[1],lens[3],... in [1,2048] -> !=0
// ---------------------------------------------------------------------------
__device__ __forceinline__ long long read_xlen(const void* p, int n) {
    const int* w = (const int*)p;
    bool is64 = true;
#pragma unroll
    for (int i = 1; i < 16; i += 2) {
        if (w[i] != 0) { is64 = false; break; }
    }
    if (is64) return ((const long long*)p)[n];
    return (long long)w[n];
}

// ---------------------------------------------------------------------------
// Single persistent kernel: mask -> barrier -> scan -> barrier -> gather.
// ---------------------------------------------------------------------------
__global__ void __launch_bounds__(TPB)
frame_reducer_kernel(const float* __restrict__ x,
                     const void* __restrict__ x_lens,
                     const float* __restrict__ ctc,
                     const int* __restrict__ blank_ptr,
                     float* __restrict__ out,
                     int t_prime, int rem, int nblocks) {
    const int lane = threadIdx.x & 31;

    // ---------------- Phase A: mask (ballot words over all (n, t)) ----------
    {
        const int blank = blank_ptr ? blank_ptr[0] : 0;
        const int nwarps = nblocks * (TPB / 32);
        int w = blockIdx.x * (TPB / 32) + (threadIdx.x >> 5);
        for (; w < PN * NWORDS; w += nwarps) {
            const int n = w >> 6;               // w / NWORDS
            const int word = w & (NWORDS - 1);
            const int t = word * 32 + lane;
            const long long xl = read_xlen(x_lens, n);
            bool k = false;
            if ((long long)t < xl) {
                k = (ctc[((size_t)n * PT + t) * PV + blank] < LOG09);
            }
            const unsigned m = __ballot_sync(0xffffffffu, k);
            if (lane == 0) g_mask[w] = m;
        }
    }

    grid_barrier(nblocks);

    // ---------------- Phase B: per-row scan (blocks 0..15, 64 threads) ------
    if (blockIdx.x < PN && threadIdx.x < 64) {
        const int n = blockIdx.x;
        const int tid = threadIdx.x;            // 0..63
        const int wrp = tid >> 5;

        const unsigned m = __ldcg(&g_mask[n * NWORDS + tid]);
        const int c = __popc(m);

        int incl = c;                           // inclusive warp scan
#pragma unroll
        for (int off = 1; off < 32; off <<= 1) {
            int v = __shfl_up_sync(0xffffffffu, incl, off);
            if ((tid & 31) >= off) incl += v;
        }

        __shared__ int warp_tot[2];
        if ((tid & 31) == 31) warp_tot[wrp] = incl;
        __syncthreads();

        int base = incl - c + (wrp == 1 ? warp_tot[0] : 0);
        const int total = warp_tot[0] + warp_tot[1];

        if (tid == 0) {
            g_lens[n] = total;
            if (rem > 0) {                      // lens tail (second output)
                const size_t off = (size_t)PN * t_prime * PC;
                if (rem == PN) {
                    out[off + n] = (float)total;
                } else if (rem == 2 * PN) {
                    reinterpret_cast<long long*>(out + off)[n] = (long long)total;
                }
            }
        }

        unsigned mm = m;
        const int t0 = tid * 32;
        while (mm) {
            const int b = __ffs(mm) - 1;
            mm &= mm - 1;
            g_src[n * PT + base] = t0 + b;
            base++;
        }
    }

    grid_barrier(nblocks);

    // ---------------- Phase C: gather / zero-fill ---------------------------
    {
        const int total_rows = PN * t_prime;
        const int sub = threadIdx.x >> 7;        // 0 or 1: which row in the pair
        const int l128 = threadIdx.x & 127;      // float4 lane within row
        for (int row0 = blockIdx.x * 2; row0 < total_rows; row0 += nblocks * 2) {
            const int row = row0 + sub;
            if (row < total_rows) {
                const int n = row / t_prime;
                const int r = row - n * t_prime;
                float4 val = make_float4(0.f, 0.f, 0.f, 0.f);
                if (r < __ldcg(&g_lens[n])) {
                    const int t = __ldcg(&g_src[n * PT + r]);
                    val = reinterpret_cast<const float4*>(
                              x + ((size_t)n * PT + t) * PC)[l128];
                }
                reinterpret_cast<float4*>(
                    out + ((size_t)n * t_prime + r) * PC)[l128] = val;
            }
        }
    }
}

// ---------------------------------------------------------------------------
extern "C" void kernel_launch(void* const* d_in, const int* in_sizes, int n_in,
                              void* d_out, int out_size) {
    const float* x      = (const float*)d_in[0];    // [N,T,C] f32
    const void*  x_lens = d_in[1];                  // [N] i32 or i64 (detected)
    const float* ctc    = (const float*)d_in[2];    // [N,T,V] f32
    const int*   blank  = (n_in >= 4) ? (const int*)d_in[3] : nullptr;
    float*       out    = (float*)d_out;

    // T' is fixed by the harness via out_size: out_size = N*T'*C (+ lens tail)
    const int row = PN * PC;                 // 8192
    int t_prime = out_size / row;
    int rem = out_size - t_prime * row;
    if (t_prime < 1) t_prime = 1;

    // Grid = SM count so every block is co-resident (grid barrier safety).
    // Queried once and cached; deterministic across calls.
    static int nsm = 0;
    if (nsm <= 0) {
        if (cudaDeviceGetAttribute(&nsm, cudaDevAttrMultiProcessorCount, 0)
                != cudaSuccess || nsm <= 0) {
            nsm = 120;                       // conservative fallback
        }
    }

    frame_reducer_kernel<<<nsm, TPB>>>(x, x_lens, ctc, blank, out,
                                       t_prime, rem, nsm);
}

// round 6
// speedup vs baseline: 3.2561x; 3.2561x over previous
#include <cuda_runtime.h>
#include <math.h>

// Problem constants (FrameReducer: N=16, T=2048, C=512, V=500)
#define PN 16
#define PT 2048
#define PC 512
#define PV 500

// Scratch (device globals; no allocation allowed)
__device__ int g_src[PN * PT];   // g_src[n*PT + r] = source frame index t for rank r
__device__ int g_lens[PN];       // lens_fr per batch row

// threshold: float32(log(0.9)) — matches jnp float32 weak-typed comparison
#define LOG09 (-0.10536051565782628f)

// ---------------------------------------------------------------------------
// Robust x_lens read: JAX with x64 disabled dumps int32 despite astype(int64).
// Detect dtype from the first 64 bytes only (always in-bounds):
//   int64 layout: words[1,3,...,15] are high words of values in [1,2048] -> 0
//   int32 layout: words[1,3,...,15] are lens[1],lens[3],... in [1,2048] -> !=0
// ---------------------------------------------------------------------------
__device__ __forceinline__ long long read_xlen(const void* p, int n) {
    const int* w = (const int*)p;
    bool is64 = true;
#pragma unroll
    for (int i = 1; i < 16; i += 2) {
        if (w[i] != 0) { is64 = false; break; }
    }
    if (is64) return ((const long long*)p)[n];
    return (long long)w[n];
}

// ---------------------------------------------------------------------------
// Kernel 1: per-row mask + stable compaction scan + lens outputs.
// One block per n, 1024 threads, 2 t-positions per thread (MLP=2, no
// serialized load chain). Warp w owns t in [64w, 64w+64): two ballots,
// parallel emission via popc-rank. Also writes the lens tail (2nd output).
// ---------------------------------------------------------------------------
__global__ void __launch_bounds__(1024)
mask_scan_kernel(const float* __restrict__ ctc,
                 const void* __restrict__ x_lens,
                 const int* __restrict__ blank_ptr,
                 float* __restrict__ out,
                 int t_prime, int rem) {
    const int n    = blockIdx.x;
    const int tid  = threadIdx.x;
    const int warp = tid >> 5;                 // 0..31
    const int lane = tid & 31;
    const int blank = blank_ptr ? blank_ptr[0] : 0;
    const long long xl = read_xlen(x_lens, n);

    const int t0 = warp * 64 + lane;
    const int t1 = t0 + 32;

    // two independent scattered loads (stride 2000B) -> MLP=2
    bool k0 = false, k1 = false;
    if ((long long)t0 < xl)
        k0 = (ctc[((size_t)n * PT + t0) * PV + blank] < LOG09);
    if ((long long)t1 < xl)
        k1 = (ctc[((size_t)n * PT + t1) * PV + blank] < LOG09);

    const unsigned b0 = __ballot_sync(0xffffffffu, k0);
    const unsigned b1 = __ballot_sync(0xffffffffu, k1);
    const int cnt = __popc(b0) + __popc(b1);

    __shared__ int wcnt[32];
    __shared__ int wbase[33];                  // [32] exclusive bases, [32]=total
    if (lane == 0) wcnt[warp] = cnt;
    __syncthreads();

    if (warp == 0) {                           // warp 0 scans the 32 warp counts
        const int v = wcnt[lane];
        int incl = v;
#pragma unroll
        for (int off = 1; off < 32; off <<= 1) {
            int u = __shfl_up_sync(0xffffffffu, incl, off);
            if (lane >= off) incl += u;
        }
        wbase[lane] = incl - v;
        if (lane == 31) wbase[32] = incl;      // row total = lens_fr[n]
    }
    __syncthreads();

    const unsigned lt = (1u << lane) - 1u;
    const int base0 = wbase[warp];
    const int base1 = base0 + __popc(b0);
    if (k0) g_src[n * PT + base0 + __popc(b0 & lt)] = t0;
    if (k1) g_src[n * PT + base1 + __popc(b1 & lt)] = t1;

    if (tid == 0) {
        const int total = wbase[32];
        g_lens[n] = total;
        if (rem > 0) {                         // lens tail (second output)
            const size_t off = (size_t)PN * t_prime * PC;
            if (rem == PN) {
                out[off + n] = (float)total;
            } else if (rem == 2 * PN) {
                reinterpret_cast<long long*>(out + off)[n] = (long long)total;
            }
        }
    }
}

// ---------------------------------------------------------------------------
// Kernel 2: gather/zero-fill. One block per output row (n, r), 128 threads,
// float4 => 128*16B = 2048B = one row of C=512 floats. Every output element
// written exactly once (no memset needed; d_out is poisoned).
// ---------------------------------------------------------------------------
__global__ void gather_kernel(const float* __restrict__ x,
                              float* __restrict__ out,
                              int t_prime) {
    const int r = blockIdx.x % t_prime;
    const int n = blockIdx.x / t_prime;
    const int lane = threadIdx.x;                // 0..127

    float4 val = make_float4(0.f, 0.f, 0.f, 0.f);
    if (r < g_lens[n]) {
        const int t = g_src[n * PT + r];
        val = reinterpret_cast<const float4*>(x + ((size_t)n * PT + t) * PC)[lane];
    }
    reinterpret_cast<float4*>(out + ((size_t)n * t_prime + r) * PC)[lane] = val;
}

// ---------------------------------------------------------------------------
extern "C" void kernel_launch(void* const* d_in, const int* in_sizes, int n_in,
                              void* d_out, int out_size) {
    const float* x      = (const float*)d_in[0];    // [N,T,C] f32
    const void*  x_lens = d_in[1];                  // [N] i32 or i64 (detected)
    const float* ctc    = (const float*)d_in[2];    // [N,T,V] f32
    const int*   blank  = (n_in >= 4) ? (const int*)d_in[3] : nullptr;
    float*       out    = (float*)d_out;

    // T' is fixed by the harness via out_size: out_size = N*T'*C (+ lens tail)
    const int row = PN * PC;                 // 8192
    int t_prime = out_size / row;
    int rem = out_size - t_prime * row;
    if (t_prime < 1) t_prime = 1;

    mask_scan_kernel<<<PN, 1024>>>(ctc, x_lens, blank, out, t_prime, rem);
    gather_kernel<<<PN * t_prime, 128>>>(x, out, t_prime);
}

// round 7
// speedup vs baseline: 4.1563x; 1.2764x over previous
#include <cuda_runtime.h>
#include <math.h>

// Problem constants (FrameReducer: N=16, T=2048, C=512, V=500)
#define PN 16
#define PT 2048
#define PC 512
#define PV 500
#define RPB 8          // rows per gather block

// Scratch (device globals; no allocation allowed)
__device__ int g_src[PN * PT];   // g_src[n*PT + r] = source frame index t for rank r
__device__ int g_lens[PN];       // lens_fr per batch row

// threshold: float32(log(0.9)) — matches jnp float32 weak-typed comparison
#define LOG09 (-0.10536051565782628f)

// ---------------------------------------------------------------------------
// Robust x_lens read: JAX with x64 disabled dumps int32 despite astype(int64).
// Detect dtype from the first 64 bytes only (always in-bounds):
//   int64 layout: words[1,3,...,15] are high words of values in [1,2048] -> 0
//   int32 layout: words[1,3,...,15] are lens[1],lens[3],... in [1,2048] -> !=0
// ---------------------------------------------------------------------------
__device__ __forceinline__ long long read_xlen(const void* p, int n) {
    const int* w = (const int*)p;
    bool is64 = true;
#pragma unroll
    for (int i = 1; i < 16; i += 2) {
        if (w[i] != 0) { is64 = false; break; }
    }
    if (is64) return ((const long long*)p)[n];
    return (long long)w[n];
}

// ---------------------------------------------------------------------------
// Kernel 1: per-row mask + stable compaction scan + lens outputs.
// One block per n, 1024 threads, 2 t-positions per thread (MLP=2).
// Warp w owns t in [64w, 64w+64): two ballots, parallel popc-rank emission.
// Also writes the lens tail (2nd output).
// ---------------------------------------------------------------------------
__global__ void __launch_bounds__(1024)
mask_scan_kernel(const float* __restrict__ ctc,
                 const void* __restrict__ x_lens,
                 const int* __restrict__ blank_ptr,
                 float* __restrict__ out,
                 int t_prime, int rem) {
    const int n    = blockIdx.x;
    const int tid  = threadIdx.x;
    const int warp = tid >> 5;                 // 0..31
    const int lane = tid & 31;
    const int blank = blank_ptr ? blank_ptr[0] : 0;
    const long long xl = read_xlen(x_lens, n);

    const int t0 = warp * 64 + lane;
    const int t1 = t0 + 32;

    bool k0 = false, k1 = false;
    if ((long long)t0 < xl)
        k0 = (ctc[((size_t)n * PT + t0) * PV + blank] < LOG09);
    if ((long long)t1 < xl)
        k1 = (ctc[((size_t)n * PT + t1) * PV + blank] < LOG09);

    const unsigned b0 = __ballot_sync(0xffffffffu, k0);
    const unsigned b1 = __ballot_sync(0xffffffffu, k1);
    const int cnt = __popc(b0) + __popc(b1);

    __shared__ int wcnt[32];
    __shared__ int wbase[33];                  // [32] exclusive bases, [32]=total
    if (lane == 0) wcnt[warp] = cnt;
    __syncthreads();

    if (warp == 0) {                           // warp 0 scans the 32 warp counts
        const int v = wcnt[lane];
        int incl = v;
#pragma unroll
        for (int off = 1; off < 32; off <<= 1) {
            int u = __shfl_up_sync(0xffffffffu, incl, off);
            if (lane >= off) incl += u;
        }
        wbase[lane] = incl - v;
        if (lane == 31) wbase[32] = incl;      // row total = lens_fr[n]
    }
    __syncthreads();

    const unsigned lt = (1u << lane) - 1u;
    const int base0 = wbase[warp];
    const int base1 = base0 + __popc(b0);
    if (k0) g_src[n * PT + base0 + __popc(b0 & lt)] = t0;
    if (k1) g_src[n * PT + base1 + __popc(b1 & lt)] = t1;

    if (tid == 0) {
        const int total = wbase[32];
        g_lens[n] = total;
        if (rem > 0) {                         // lens tail (second output)
            const size_t off = (size_t)PN * t_prime * PC;
            if (rem == PN) {
                out[off + n] = (float)total;
            } else if (rem == 2 * PN) {
                reinterpret_cast<long long*>(out + off)[n] = (long long)total;
            }
        }
    }
}

// ---------------------------------------------------------------------------
// Kernel 2: gather/zero-fill. 8 rows per 256-thread block.
// Output address is row-major in the flat row index (n*t_prime + r), so
// stores need no div/mod. Threads 0..7 resolve the 8 source frame offsets
// into shared once (-1 => zero row); then each thread does 4 INDEPENDENT
// float4 load->store pairs (MLP=4). Every output element written exactly
// once (no memset; d_out is poisoned).
// ---------------------------------------------------------------------------
__global__ void __launch_bounds__(256)
gather_kernel(const float* __restrict__ x,
              float* __restrict__ out,
              int t_prime, int total_rows) {
    __shared__ int s_off[RPB];                 // source frame index n*PT+t, or -1

    const int row0 = blockIdx.x * RPB;
    const int tid  = threadIdx.x;

    if (tid < RPB) {
        const int row = row0 + tid;
        int off = -1;
        if (row < total_rows) {
            const int n = row / t_prime;
            const int r = row - n * t_prime;
            if (r < g_lens[n]) off = n * PT + g_src[n * PT + r];
        }
        s_off[tid] = off;
    }
    __syncthreads();

    const int lane = tid & 127;                // float4 lane within a row
    const int half = tid >> 7;                 // 0 or 1

    int   offs[4];
    float4 vals[4];
#pragma unroll
    for (int i = 0; i < 4; i++) {
        offs[i] = s_off[half + 2 * i];
    }
#pragma unroll
    for (int i = 0; i < 4; i++) {              // 4 independent loads, batched
        vals[i] = make_float4(0.f, 0.f, 0.f, 0.f);
        if (offs[i] >= 0) {
            vals[i] = reinterpret_cast<const float4*>(
                          x + (size_t)offs[i] * PC)[lane];
        }
    }
#pragma unroll
    for (int i = 0; i < 4; i++) {
        const int row = row0 + half + 2 * i;
        if (row < total_rows) {
            reinterpret_cast<float4*>(out + (size_t)row * PC)[lane] = vals[i];
        }
    }
}

// ---------------------------------------------------------------------------
extern "C" void kernel_launch(void* const* d_in, const int* in_sizes, int n_in,
                              void* d_out, int out_size) {
    const float* x      = (const float*)d_in[0];    // [N,T,C] f32
    const void*  x_lens = d_in[1];                  // [N] i32 or i64 (detected)
    const float* ctc    = (const float*)d_in[2];    // [N,T,V] f32
    const int*   blank  = (n_in >= 4) ? (const int*)d_in[3] : nullptr;
    float*       out    = (float*)d_out;

    // T' is fixed by the harness via out_size: out_size = N*T'*C (+ lens tail)
    const int row = PN * PC;                 // 8192
    int t_prime = out_size / row;
    int rem = out_size - t_prime * row;
    if (t_prime < 1) t_prime = 1;

    const int total_rows = PN * t_prime;
    const int nblk = (total_rows + RPB - 1) / RPB;

    mask_scan_kernel<<<PN, 1024>>>(ctc, x_lens, blank, out, t_prime, rem);
    gather_kernel<<<nblk, 256>>>(x, out, t_prime, total_rows);
}